// round 1
// baseline (speedup 1.0000x reference)
#include <cuda_runtime.h>
#include <cstdint>

// Problem constants
#define NB   64
#define C    256
#define HH   28
#define WW   28
#define HW   784                 // 28*28
#define MTOT (NB*HW)             // 50176
#define KK9  9

// Tiling
#define BM 128
#define BN 128
#define BK 32
#define NKCH (KK9 * (C/BK))      // 72 k-chunks

// Shared layout (floats)
#define SA_STRIDE 36             // 32 + pad; conflict-free A frag loads
#define SB_STRIDE 136            // 128 + pad; conflict-free B frag loads
#define ST_STRIDE 132            // epilogue transpose stride (conflict-free writes, LDS.128 reads)
#define SA_SZ (BM*SA_STRIDE)     // 4608
#define SB_SZ (BK*SB_STRIDE)     // 4352
#define STAGE_SZ (SA_SZ + SB_SZ) // 8960
#define SMEM_FLOATS (2*STAGE_SZ) // 17920
#define SMEM_BYTES (SMEM_FLOATS*4) // 71680

// Scratch (device globals; allocation in kernel_launch is forbidden)
__device__ float g_xh[(size_t)MTOT * C];     // x in NHWC, tf32-rounded
__device__ float g_out1[(size_t)MTOT * C];   // conv1 output NHWC, tf32-rounded
__device__ float g_wp1[KK9 * C * C];         // sign(w1) as [kk][ci][co]
__device__ float g_wp2[KK9 * C * C];
__device__ float g_s1[C], g_bb1[C], g_s2[C], g_bb2[C];

// ---------------------------------------------------------------------------
__device__ __forceinline__ float to_tf32(float x) {
    unsigned u;
    asm volatile("cvt.rna.tf32.f32 %0, %1;\n" : "=r"(u) : "f"(x));
    return __uint_as_float(u);
}

__device__ __forceinline__ void cp16(float* dst, const float* src, bool pred) {
    unsigned d = (unsigned)__cvta_generic_to_shared(dst);
    int sz = pred ? 16 : 0;
    asm volatile("cp.async.ca.shared.global [%0], [%1], 16, %2;\n"
                 :: "r"(d), "l"(src), "r"(sz));
}
__device__ __forceinline__ void cp_commit() { asm volatile("cp.async.commit_group;\n" ::); }
__device__ __forceinline__ void cp_wait1()  { asm volatile("cp.async.wait_group 1;\n" ::); }

__device__ __forceinline__ void mma_tf32(float* c, const unsigned* a, const unsigned* b) {
    asm volatile(
        "mma.sync.aligned.m16n8k8.row.col.f32.tf32.tf32.f32 "
        "{%0,%1,%2,%3}, {%4,%5,%6,%7}, {%8,%9}, {%0,%1,%2,%3};\n"
        : "+f"(c[0]), "+f"(c[1]), "+f"(c[2]), "+f"(c[3])
        : "r"(a[0]), "r"(a[1]), "r"(a[2]), "r"(a[3]), "r"(b[0]), "r"(b[1]));
}

// ---------------------------------------------------------------------------
// Fold BN constants: y = acc * (SCALE*g*rsqrt(v+eps)) + (b - m*g*rsqrt(v+eps))
__global__ void bn_prep(const float* __restrict__ g1, const float* __restrict__ b1,
                        const float* __restrict__ m1, const float* __restrict__ v1,
                        const float* __restrict__ g2, const float* __restrict__ b2,
                        const float* __restrict__ m2, const float* __restrict__ v2) {
    int t = threadIdx.x;
    if (t < C) {
        float inv1 = g1[t] * rsqrtf(v1[t] + 1e-5f);
        g_s1[t]  = 0.02f * inv1;
        g_bb1[t] = b1[t] - m1[t] * inv1;
        float inv2 = g2[t] * rsqrtf(v2[t] + 1e-5f);
        g_s2[t]  = 0.02f * inv2;
        g_bb2[t] = b2[t] - m2[t] * inv2;
    }
}

// NCHW -> NHWC transpose with tf32 rounding. block (32,8), grid (25, 8, 64)
__global__ void xpose(const float* __restrict__ x) {
    __shared__ float t[32][33];
    int n = blockIdx.z, hwt = blockIdx.x, ct = blockIdx.y;
    int tx = threadIdx.x, ty = threadIdx.y;
    int hw = hwt * 32 + tx;
    #pragma unroll
    for (int i = 0; i < 4; i++) {
        int c = ct * 32 + ty + i * 8;
        t[ty + i * 8][tx] = (hw < HW) ? x[((size_t)n * C + c) * HW + hw] : 0.f;
    }
    __syncthreads();
    #pragma unroll
    for (int i = 0; i < 4; i++) {
        int hw2 = hwt * 32 + ty + i * 8;
        int c = ct * 32 + tx;
        if (hw2 < HW)
            g_xh[((size_t)n * HW + hw2) * C + c] = to_tf32(t[tx][ty + i * 8]);
    }
}

// sign(w) packed [kk][ci][co]; sign(0)=0 to match jnp.sign exactly.
__global__ void packw(const float* __restrict__ w, int which) {
    int idx = blockIdx.x * 256 + threadIdx.x;     // < 9*256*256 = 589824
    int kk  = idx >> 16;
    int rem = idx & 65535;
    int ci  = rem >> 8;
    int co  = rem & 255;
    float wv = w[co * (C * 9) + ci * 9 + kk];
    float s = (wv > 0.f) ? 1.f : ((wv < 0.f) ? -1.f : 0.f);
    if (which == 0) g_wp1[idx] = s; else g_wp2[idx] = s;
}

// ---------------------------------------------------------------------------
// Implicit-GEMM 3x3 conv (pad 1) with +-1 weights.
// MODE 0: A=g_xh,  W=g_wp1, out = relu(bn1(conv))  -> g_out1 (NHWC, tf32)
// MODE 1: A=g_out1,W=g_wp2, out = relu(bn2(conv)+x)-> d_out  (NCHW fp32)
template <int MODE>
__global__ void __launch_bounds__(256, 1)
convk(const float* __restrict__ resid, float* __restrict__ out) {
    extern __shared__ float smem[];
    const float* Ain = (MODE == 0) ? g_xh  : g_out1;
    const float* Wp  = (MODE == 0) ? g_wp1 : g_wp2;
    const float* sc  = (MODE == 0) ? g_s1  : g_s2;
    const float* bi  = (MODE == 0) ? g_bb1 : g_bb2;

    const int tid = threadIdx.x;
    const int bn  = blockIdx.x;   // 0..1   (co tile)
    const int bm  = blockIdx.y;   // 0..391 (m tile)

    float* sA[2] = { smem,         smem + STAGE_SZ };
    float* sB[2] = { smem + SA_SZ, smem + STAGE_SZ + SA_SZ };

    // --- A-load geometry (fixed per thread) ---
    const int arow = tid >> 3;            // 0..31
    const int acol = (tid & 7) * 4;       // 0,4,...,28
    int ah[4], aw[4];
    long rowoff[4];
    #pragma unroll
    for (int p = 0; p < 4; p++) {
        int m = bm * BM + arow + p * 32;
        int n = m / HW;
        int hw = m - n * HW;
        ah[p] = hw / WW;
        aw[p] = hw - ah[p] * WW;
        rowoff[p] = (long)m * C + acol;   // (n*784 + h*28 + w)*256 + acol
    }
    // --- B-load geometry ---
    const int brow = tid >> 5;            // 0..7
    const int bcol = (tid & 31) * 4;

    auto loadA = [&](int st, int kc) {
        int kk = kc >> 3, ck = kc & 7;
        int kd = kk / 3;
        int dh = kd - 1, dw = (kk - kd * 3) - 1;
        long koff = (long)(dh * WW + dw) * C + ck * BK;
        #pragma unroll
        for (int p = 0; p < 4; p++) {
            int ih = ah[p] + dh, iw = aw[p] + dw;
            bool v = ((unsigned)ih < HH) && ((unsigned)iw < WW);
            const float* src = v ? (Ain + rowoff[p] + koff) : Ain;
            cp16(sA[st] + (arow + p * 32) * SA_STRIDE + acol, src, v);
        }
    };
    auto loadB = [&](int st, int kc) {
        int kk = kc >> 3, ck = kc & 7;
        const float* base = Wp + kk * (C * C) + (ck * BK) * C + bn * BN;
        #pragma unroll
        for (int p = 0; p < 4; p++)
            cp16(sB[st] + (brow + p * 8) * SB_STRIDE + bcol,
                 base + (brow + p * 8) * C + bcol, true);
    };

    float acc[4][4][4];
    #pragma unroll
    for (int i = 0; i < 4; i++)
        #pragma unroll
        for (int j = 0; j < 4; j++)
            #pragma unroll
            for (int k = 0; k < 4; k++) acc[i][j][k] = 0.f;

    const int warp = tid >> 5, lane = tid & 31;
    const int wm = warp >> 2, wn = warp & 3;   // 2 x 4 warp grid
    const int grp = lane >> 2, tig = lane & 3;

    loadA(0, 0); loadB(0, 0); cp_commit();

    for (int kc = 0; kc < NKCH; kc++) {
        int st = kc & 1;
        if (kc + 1 < NKCH) { loadA(st ^ 1, kc + 1); loadB(st ^ 1, kc + 1); }
        cp_commit();
        cp_wait1();
        __syncthreads();
        const float* cA = sA[st];
        const float* cB = sB[st];
        #pragma unroll
        for (int ks = 0; ks < 4; ks++) {
            unsigned afr[4][4];
            #pragma unroll
            for (int mt = 0; mt < 4; mt++) {
                int r0 = wm * 64 + mt * 16 + grp;
                int kb = ks * 8;
                afr[mt][0] = __float_as_uint(cA[r0 * SA_STRIDE + kb + tig]);
                afr[mt][1] = __float_as_uint(cA[(r0 + 8) * SA_STRIDE + kb + tig]);
                afr[mt][2] = __float_as_uint(cA[r0 * SA_STRIDE + kb + tig + 4]);
                afr[mt][3] = __float_as_uint(cA[(r0 + 8) * SA_STRIDE + kb + tig + 4]);
            }
            unsigned bfr[4][2];
            #pragma unroll
            for (int nt = 0; nt < 4; nt++) {
                int cc = wn * 32 + nt * 8 + grp;
                bfr[nt][0] = __float_as_uint(cB[(ks * 8 + tig) * SB_STRIDE + cc]);
                bfr[nt][1] = __float_as_uint(cB[(ks * 8 + tig + 4) * SB_STRIDE + cc]);
            }
            #pragma unroll
            for (int mt = 0; mt < 4; mt++)
                #pragma unroll
                for (int nt = 0; nt < 4; nt++)
                    mma_tf32(acc[mt][nt], afr[mt], bfr[nt]);
        }
        __syncthreads();
    }

    // ------------------------------ epilogue -------------------------------
    if (MODE == 0) {
        // BN + ReLU, store NHWC tf32-rounded (input of conv2)
        #pragma unroll
        for (int nt = 0; nt < 4; nt++) {
            int col = bn * BN + wn * 32 + nt * 8 + tig * 2;
            float s0 = sc[col], s1 = sc[col + 1];
            float c0 = bi[col], c1 = bi[col + 1];
            #pragma unroll
            for (int mt = 0; mt < 4; mt++) {
                int m0 = bm * BM + wm * 64 + mt * 16 + grp;
                float v0 = fmaxf(acc[mt][nt][0] * s0 + c0, 0.f);
                float v1 = fmaxf(acc[mt][nt][1] * s1 + c1, 0.f);
                float v2 = fmaxf(acc[mt][nt][2] * s0 + c0, 0.f);
                float v3 = fmaxf(acc[mt][nt][3] * s1 + c1, 0.f);
                float2 lo = make_float2(to_tf32(v0), to_tf32(v1));
                float2 hi = make_float2(to_tf32(v2), to_tf32(v3));
                *(float2*)&g_out1[(size_t)m0 * C + col] = lo;
                *(float2*)&g_out1[(size_t)(m0 + 8) * C + col] = hi;
            }
        }
    } else {
        // BN + residual + ReLU, coalesced NCHW store via smem transpose.
        float* st = smem;  // 32 x ST_STRIDE floats, fits in sA stage 0
        #pragma unroll
        for (int c = 0; c < 4; c++) {          // 32-co chunk
            __syncthreads();
            if (wn == c) {
                #pragma unroll
                for (int nt = 0; nt < 4; nt++) {
                    int col_l = nt * 8 + tig * 2;
                    int col = bn * BN + c * 32 + col_l;
                    float s0 = sc[col], s1 = sc[col + 1];
                    float c0 = bi[col], c1 = bi[col + 1];
                    #pragma unroll
                    for (int mt = 0; mt < 4; mt++) {
                        int ml = wm * 64 + mt * 16 + grp;
                        st[col_l * ST_STRIDE + ml]           = acc[mt][nt][0] * s0 + c0;
                        st[(col_l + 1) * ST_STRIDE + ml]     = acc[mt][nt][1] * s1 + c1;
                        st[col_l * ST_STRIDE + ml + 8]       = acc[mt][nt][2] * s0 + c0;
                        st[(col_l + 1) * ST_STRIDE + ml + 8] = acc[mt][nt][3] * s1 + c1;
                    }
                }
            }
            __syncthreads();
            #pragma unroll
            for (int j = 0; j < 4; j++) {
                int col_l = warp + j * 8;
                int co = bn * BN + c * 32 + col_l;
                int ml4 = lane * 4;
                int mg = bm * BM + ml4;
                int n = mg / HW;
                int hw = mg - n * HW;
                size_t gi = ((size_t)n * C + co) * HW + hw;
                float4 r = *(const float4*)&resid[gi];
                float4 sv = *(const float4*)&st[col_l * ST_STRIDE + ml4];
                float4 v;
                v.x = fmaxf(sv.x + r.x, 0.f);
                v.y = fmaxf(sv.y + r.y, 0.f);
                v.z = fmaxf(sv.z + r.z, 0.f);
                v.w = fmaxf(sv.w + r.w, 0.f);
                *(float4*)&out[gi] = v;
            }
        }
    }
}

// ---------------------------------------------------------------------------
extern "C" void kernel_launch(void* const* d_in, const int* in_sizes, int n_in,
                              void* d_out, int out_size) {
    (void)in_sizes; (void)n_in; (void)out_size;
    const float* x  = (const float*)d_in[0];
    const float* w1 = (const float*)d_in[1];
    const float* g1 = (const float*)d_in[2];
    const float* b1 = (const float*)d_in[3];
    const float* m1 = (const float*)d_in[4];
    const float* v1 = (const float*)d_in[5];
    const float* w2 = (const float*)d_in[6];
    const float* g2 = (const float*)d_in[7];
    const float* b2 = (const float*)d_in[8];
    const float* m2 = (const float*)d_in[9];
    const float* v2 = (const float*)d_in[10];
    float* out = (float*)d_out;

    cudaFuncSetAttribute(convk<0>, cudaFuncAttributeMaxDynamicSharedMemorySize, SMEM_BYTES);
    cudaFuncSetAttribute(convk<1>, cudaFuncAttributeMaxDynamicSharedMemorySize, SMEM_BYTES);

    bn_prep<<<1, 256>>>(g1, b1, m1, v1, g2, b2, m2, v2);
    xpose<<<dim3(25, 8, 64), dim3(32, 8)>>>(x);
    packw<<<2304, 256>>>(w1, 0);
    packw<<<2304, 256>>>(w2, 1);

    dim3 grid(C / BN, MTOT / BM);   // (2, 392)
    convk<0><<<grid, 256, SMEM_BYTES>>>(nullptr, nullptr);
    convk<1><<<grid, 256, SMEM_BYTES>>>(x, out);
}

// round 3
// speedup vs baseline: 2.0258x; 2.0258x over previous
#include <cuda_runtime.h>
#include <cuda_fp16.h>
#include <cstdint>

// ---------------- problem constants ----------------
#define NB   64
#define C    256
#define HH   28
#define WW   28
#define HW   784
#define MTOT (NB*HW)          // 50176

// ---------------- tiling ----------------
#define BM   256
#define BN   128
#define BK   64
#define NTILES (MTOT/BM)      // 196
#define NKCH 36               // 9 kk * 4 ci-chunks of 64

#define STAGES 3
#define A_BYTES (BM*128)      // 32 KB  (256 rows x 64 fp16 = 128B)
#define B_BYTES (BN*128)      // 16 KB
#define STG (A_BYTES + B_BYTES)
#define SMEM_BYTES (STAGES*STG)   // 147456

// ---------------- scratch ----------------
__device__ __half g_xh[(size_t)MTOT * C];    // x NHWC fp16
__device__ __half g_out1[(size_t)MTOT * C];  // conv1 out NHWC fp16
__device__ __half g_wp1[9 * C * C];          // sign(w1) [kk][co][ci]
__device__ __half g_wp2[9 * C * C];
__device__ float g_s1[C], g_bb1[C], g_s2[C], g_bb2[C];

// ---------------- ptx helpers ----------------
__device__ __forceinline__ uint32_t smem_u32(const void* p) {
    uint32_t a;
    asm("{ .reg .u64 t; cvta.to.shared.u64 t, %1; cvt.u32.u64 %0, t; }" : "=r"(a) : "l"(p));
    return a;
}
__device__ __forceinline__ void cp16(uint32_t dst, const void* src, bool pred) {
    int sz = pred ? 16 : 0;
    asm volatile("cp.async.cg.shared.global [%0], [%1], 16, %2;\n"
                 :: "r"(dst), "l"(src), "r"(sz));
}
__device__ __forceinline__ void cp_commit() { asm volatile("cp.async.commit_group;\n" ::); }
__device__ __forceinline__ void cp_wait2()  { asm volatile("cp.async.wait_group 2;\n" ::: "memory"); }

__device__ __forceinline__ void ldmx4(uint32_t* r, uint32_t addr) {
    asm volatile("ldmatrix.sync.aligned.m8n8.x4.shared.b16 {%0,%1,%2,%3}, [%4];"
        : "=r"(r[0]), "=r"(r[1]), "=r"(r[2]), "=r"(r[3]) : "r"(addr));
}
__device__ __forceinline__ void mma16816(float* c, const uint32_t* a, const uint32_t* b) {
    asm volatile("mma.sync.aligned.m16n8k16.row.col.f32.f16.f16.f32 "
        "{%0,%1,%2,%3}, {%4,%5,%6,%7}, {%8,%9}, {%0,%1,%2,%3};"
        : "+f"(c[0]), "+f"(c[1]), "+f"(c[2]), "+f"(c[3])
        : "r"(a[0]), "r"(a[1]), "r"(a[2]), "r"(a[3]), "r"(b[0]), "r"(b[1]));
}
#define SW(off) ((off) ^ (((off) >> 3) & 0x70))

// ---------------- prologue kernels ----------------
__global__ void bn_prep(const float* __restrict__ g1, const float* __restrict__ b1,
                        const float* __restrict__ m1, const float* __restrict__ v1,
                        const float* __restrict__ g2, const float* __restrict__ b2,
                        const float* __restrict__ m2, const float* __restrict__ v2) {
    int t = threadIdx.x;
    if (t < C) {
        float inv1 = g1[t] * rsqrtf(v1[t] + 1e-5f);
        g_s1[t]  = 0.02f * inv1;
        g_bb1[t] = b1[t] - m1[t] * inv1;
        float inv2 = g2[t] * rsqrtf(v2[t] + 1e-5f);
        g_s2[t]  = 0.02f * inv2;
        g_bb2[t] = b2[t] - m2[t] * inv2;
    }
}

// NCHW -> NHWC transpose, fp32 -> fp16
__global__ void xpose(const float* __restrict__ x) {
    __shared__ float t[32][33];
    int n = blockIdx.z, hwt = blockIdx.x, ct = blockIdx.y;
    int tx = threadIdx.x, ty = threadIdx.y;
    int hw = hwt * 32 + tx;
    #pragma unroll
    for (int i = 0; i < 4; i++) {
        int c = ct * 32 + ty + i * 8;
        t[ty + i * 8][tx] = (hw < HW) ? x[((size_t)n * C + c) * HW + hw] : 0.f;
    }
    __syncthreads();
    #pragma unroll
    for (int i = 0; i < 4; i++) {
        int hw2 = hwt * 32 + ty + i * 8;
        int c = ct * 32 + tx;
        if (hw2 < HW)
            g_xh[((size_t)n * HW + hw2) * C + c] = __float2half_rn(t[tx][ty + i * 8]);
    }
}

// sign(w) packed as [kk][co][ci] fp16; sign(0)=0 to match jnp.sign.
__global__ void packw(const float* __restrict__ w, int which) {
    int idx = blockIdx.x * 256 + threadIdx.x;   // < 9*256*256
    int kk  = idx >> 16;
    int rem = idx & 65535;
    int co  = rem >> 8;
    int ci  = rem & 255;
    float wv = w[(co * C + ci) * 9 + kk];
    float s = (wv > 0.f) ? 1.f : ((wv < 0.f) ? -1.f : 0.f);
    __half h = __float2half_rn(s);
    if (which == 0) g_wp1[idx] = h; else g_wp2[idx] = h;
}

// ---------------- main conv kernel (fp16 HMMA implicit GEMM) ----------------
// MODE 0: A=g_xh,  W=g_wp1, out = relu(bn1(conv))   -> g_out1 (NHWC fp16)
// MODE 1: A=g_out1,W=g_wp2, out = relu(bn2(conv)+x) -> d_out  (NCHW fp32)
template <int MODE>
__global__ void __launch_bounds__(256, 1)
convk(const float* __restrict__ resid, float* __restrict__ out) {
    extern __shared__ char smem[];
    const uint32_t sb = smem_u32(smem);

    const __half* Ain = MODE ? g_out1 : g_xh;
    const __half* Wp  = MODE ? g_wp2  : g_wp1;
    const float*  sc  = MODE ? g_s2   : g_s1;
    const float*  bi  = MODE ? g_bb2  : g_bb1;

    const int tid  = threadIdx.x;
    const int wid  = tid >> 5, lane = tid & 31;
    const int bn   = blockIdx.x;    // 0..1
    const int bm   = blockIdx.y;    // 0..195

    // --- loader geometry ---
    const int m  = bm * BM + tid;
    const int n  = m / HW;
    const int hw = m - n * HW;
    const int h  = hw / WW;
    const int w  = hw - h * WW;
    const __half* arow = Ain + (size_t)m * C;
    const int brow  = tid >> 1;
    const int bhalf = tid & 1;
    const __half* bbase = Wp + (size_t)(bn * BN + brow) * C + bhalf * 32;

    auto loadStage = [&](int kc) {
        const int s  = kc % STAGES;
        const int kk = kc >> 2, ck = kc & 3;
        const int dh = kk / 3 - 1;
        const int dw = kk - (kk / 3) * 3 - 1;
        const uint32_t aB = sb + s * STG;
        const uint32_t bB = aB + A_BYTES;

        const bool valid = ((unsigned)(h + dh) < HH) && ((unsigned)(w + dw) < WW);
        const __half* asrc = valid ? (arow + (dh * WW + dw) * C + ck * 64) : (const __half*)Wp;
        const uint32_t ra = (uint32_t)tid * 128;
        #pragma unroll
        for (int i = 0; i < 8; i++) {
            uint32_t off = ra + i * 16;
            cp16(aB + SW(off), asrc + i * 8, valid);
        }
        const __half* bs = bbase + (size_t)kk * (C * C) + ck * 64;
        const uint32_t rb = (uint32_t)brow * 128 + bhalf * 64;
        #pragma unroll
        for (int i = 0; i < 4; i++) {
            uint32_t off = rb + i * 16;
            cp16(bB + SW(off), bs + i * 8, true);
        }
        cp_commit();
    };

    // --- compute geometry ---
    const int wm = wid >> 1;          // 0..3  (m 64-tile)
    const int wn = wid & 1;           // 0..1  (n 64-tile)
    const int lq = lane >> 3;         // quad
    const int l7 = lane & 7;
    const int aro = (lq & 1) * 8 + l7;     // A ldmatrix row offset
    const int aqh = lq >> 1;               // A k-16B-half select
    const int bro = (lq >> 1) * 8 + l7;    // B ldmatrix row offset
    const int bqh = lq & 1;                // B k-16B-half select

    float acc[4][8][4];
    #pragma unroll
    for (int i = 0; i < 4; i++)
        #pragma unroll
        for (int j = 0; j < 8; j++)
            #pragma unroll
            for (int k = 0; k < 4; k++) acc[i][j][k] = 0.f;

    loadStage(0);
    loadStage(1);

    for (int kc = 0; kc < NKCH; kc++) {
        if (kc + 2 < NKCH) loadStage(kc + 2); else cp_commit();
        cp_wait2();
        __syncthreads();

        const int s = kc % STAGES;
        const uint32_t aB = sb + s * STG + (uint32_t)(wm * 64) * 128;
        const uint32_t bB = sb + s * STG + A_BYTES + (uint32_t)(wn * 64) * 128;

        #pragma unroll
        for (int ks = 0; ks < 4; ks++) {
            uint32_t af[4][4];
            #pragma unroll
            for (int mt = 0; mt < 4; mt++) {
                int row = mt * 16 + aro;
                uint32_t cx = (uint32_t)(((ks * 2 + aqh) ^ (row & 7)) * 16);
                ldmx4(af[mt], aB + (uint32_t)row * 128 + cx);
            }
            uint32_t bf[4][4];
            #pragma unroll
            for (int nt2 = 0; nt2 < 4; nt2++) {
                int row = nt2 * 16 + bro;
                uint32_t cx = (uint32_t)(((ks * 2 + bqh) ^ (row & 7)) * 16);
                ldmx4(bf[nt2], bB + (uint32_t)row * 128 + cx);
            }
            #pragma unroll
            for (int mt = 0; mt < 4; mt++)
                #pragma unroll
                for (int nt = 0; nt < 8; nt++)
                    mma16816(acc[mt][nt], af[mt], &bf[nt >> 1][(nt & 1) * 2]);
        }
        __syncthreads();
    }

    // ---------------- epilogue ----------------
    const int lr = lane >> 2;        // 0..7  (row in tile)
    const int lc = (lane & 3) * 2;   // col pair in tile

    if (MODE == 0) {
        const int mbase  = bm * BM + wm * 64;
        const int cobase = bn * BN + wn * 64;
        #pragma unroll
        for (int nt = 0; nt < 8; nt++) {
            const int co = cobase + nt * 8 + lc;
            const float s0 = sc[co],   s1 = sc[co + 1];
            const float c0 = bi[co],   c1 = bi[co + 1];
            #pragma unroll
            for (int mt = 0; mt < 4; mt++) {
                const int m0 = mbase + mt * 16 + lr;
                float v0 = fmaxf(acc[mt][nt][0] * s0 + c0, 0.f);
                float v1 = fmaxf(acc[mt][nt][1] * s1 + c1, 0.f);
                float v2 = fmaxf(acc[mt][nt][2] * s0 + c0, 0.f);
                float v3 = fmaxf(acc[mt][nt][3] * s1 + c1, 0.f);
                *(__half2*)&g_out1[(size_t)m0 * C + co]       = __floats2half2_rn(v0, v1);
                *(__half2*)&g_out1[(size_t)(m0 + 8) * C + co] = __floats2half2_rn(v2, v3);
            }
        }
    } else {
        // transpose through smem -> coalesced NCHW float4 stores with residual
        float* st = (float*)smem;    // [co 128][m 256] stride 260 floats
        #pragma unroll
        for (int nt = 0; nt < 8; nt++) {
            const int col = wn * 64 + nt * 8 + lc;
            const int gco = bn * BN + col;
            const float s0 = sc[gco],   s1 = sc[gco + 1];
            const float c0 = bi[gco],   c1 = bi[gco + 1];
            #pragma unroll
            for (int mt = 0; mt < 4; mt++) {
                const int ml = wm * 64 + mt * 16 + lr;
                st[col * 260 + ml]           = acc[mt][nt][0] * s0 + c0;
                st[(col + 1) * 260 + ml]     = acc[mt][nt][1] * s1 + c1;
                st[col * 260 + ml + 8]       = acc[mt][nt][2] * s0 + c0;
                st[(col + 1) * 260 + ml + 8] = acc[mt][nt][3] * s1 + c1;
            }
        }
        __syncthreads();
        #pragma unroll
        for (int p = 0; p < 4; p++) {
            const int col = p * 32 + (tid >> 3);
            const int gco = bn * BN + col;
            #pragma unroll
            for (int j = 0; j < 8; j++) {
                const int ml = ((tid & 7) + j * 8) * 4;
                const int mg = bm * BM + ml;
                const int n2 = mg / HW;
                const int hw2 = mg - n2 * HW;
                const size_t gi = (size_t)n2 * (C * HW) + (size_t)gco * HW + hw2;
                float4 r = *(const float4*)&resid[gi];
                float4 v = *(const float4*)&st[col * 260 + ml];
                float4 o;
                o.x = fmaxf(v.x + r.x, 0.f);
                o.y = fmaxf(v.y + r.y, 0.f);
                o.z = fmaxf(v.z + r.z, 0.f);
                o.w = fmaxf(v.w + r.w, 0.f);
                *(float4*)&out[gi] = o;
            }
        }
    }
}

// ---------------- launch ----------------
extern "C" void kernel_launch(void* const* d_in, const int* in_sizes, int n_in,
                              void* d_out, int out_size) {
    (void)in_sizes; (void)n_in; (void)out_size;
    const float* x  = (const float*)d_in[0];
    const float* w1 = (const float*)d_in[1];
    const float* g1 = (const float*)d_in[2];
    const float* b1 = (const float*)d_in[3];
    const float* m1 = (const float*)d_in[4];
    const float* v1 = (const float*)d_in[5];
    const float* w2 = (const float*)d_in[6];
    const float* g2 = (const float*)d_in[7];
    const float* b2 = (const float*)d_in[8];
    const float* m2 = (const float*)d_in[9];
    const float* v2 = (const float*)d_in[10];
    float* out = (float*)d_out;

    cudaFuncSetAttribute(convk<0>, cudaFuncAttributeMaxDynamicSharedMemorySize, SMEM_BYTES);
    cudaFuncSetAttribute(convk<1>, cudaFuncAttributeMaxDynamicSharedMemorySize, SMEM_BYTES);

    bn_prep<<<1, 256>>>(g1, b1, m1, v1, g2, b2, m2, v2);
    xpose<<<dim3(25, 8, 64), dim3(32, 8)>>>(x);
    packw<<<2304, 256>>>(w1, 0);
    packw<<<2304, 256>>>(w2, 1);

    dim3 grid(2, NTILES);   // (bn, bm)
    convk<0><<<grid, 256, SMEM_BYTES>>>(nullptr, nullptr);
    convk<1><<<grid, 256, SMEM_BYTES>>>(x, out);
}